// round 8
// baseline (speedup 1.0000x reference)
#include <cuda_runtime.h>
#include <cstdint>
#include <cmath>
#include <math.h>

// Problem constants (fixed by setup_inputs)
#define T_TOK    8192
#define D_MODEL  1024
#define F_FF     4096
#define N_EXP    8
#define CAPACITY 2560          // ceil(1.25 * 8192*2 / 8)
#define NASSIGN  (T_TOK * 2)

// ---------------- scratch (device globals: no allocation allowed) ----------------
__device__ int   g_expert[NASSIGN];
__device__ float g_gate[NASSIGN];
__device__ int   g_pos[NASSIGN];
__device__ int   g_count[N_EXP];
__device__ int   g_rowtok[N_EXP * CAPACITY];
__device__ float g_h[(size_t)N_EXP * CAPACITY * F_FF];    // 335 MB
__device__ float g_y[(size_t)N_EXP * CAPACITY * D_MODEL]; //  84 MB

// ---------------- small helpers ----------------
__device__ __forceinline__ uint32_t su32(const void* p) {
    return (uint32_t)__cvta_generic_to_shared(p);
}
__device__ __forceinline__ uint32_t f2tf(float f) {
    uint32_t r; asm("cvt.rna.tf32.f32 %0, %1;" : "=r"(r) : "f"(f)); return r;
}
__device__ __forceinline__ void cpa16(uint32_t d, const void* s) {
    asm volatile("cp.async.cg.shared.global [%0], [%1], 16;" :: "r"(d), "l"(s));
}
__device__ __forceinline__ void cp_commit() { asm volatile("cp.async.commit_group;"); }
__device__ __forceinline__ void cp_wait0()  { asm volatile("cp.async.wait_group 0;" ::: "memory"); }

__device__ __forceinline__ void mma_tf32(float* c, const uint32_t* a, uint32_t b0, uint32_t b1) {
    asm volatile(
        "mma.sync.aligned.m16n8k8.row.col.f32.tf32.tf32.f32 "
        "{%0,%1,%2,%3}, {%4,%5,%6,%7}, {%8,%9}, {%0,%1,%2,%3};"
        : "+f"(c[0]), "+f"(c[1]), "+f"(c[2]), "+f"(c[3])
        : "r"(a[0]), "r"(a[1]), "r"(a[2]), "r"(a[3]), "r"(b0), "r"(b1));
}

__device__ __forceinline__ float gelu_exact(float v) {
    return 0.5f * v * (1.0f + erff(v * 0.70710678118654752440f));
}

// ---------------- 1) router: logits -> top2 -> normalized weights ----------------
__global__ void router_kernel(const float* __restrict__ x,
                              const float* __restrict__ Wr,
                              const float* __restrict__ br) {
    __shared__ float sW[D_MODEL * N_EXP];  // 32 KB
    const int tid = threadIdx.x;
    for (int i = tid; i < D_MODEL * N_EXP / 4; i += blockDim.x)
        ((float4*)sW)[i] = ((const float4*)Wr)[i];
    __syncthreads();

    const int warp = tid >> 5, lane = tid & 31;
    const int tok = blockIdx.x * 8 + warp;
    const float* xr = x + (size_t)tok * D_MODEL;

    float a[8] = {0.f,0.f,0.f,0.f,0.f,0.f,0.f,0.f};
    for (int i = lane; i < D_MODEL; i += 32) {
        float xv = xr[i];
        const float* w = sW + i * N_EXP;
        #pragma unroll
        for (int e = 0; e < 8; e++) a[e] += xv * w[e];
    }
    #pragma unroll
    for (int e = 0; e < 8; e++) {
        #pragma unroll
        for (int off = 16; off; off >>= 1)
            a[e] += __shfl_xor_sync(0xffffffffu, a[e], off);
    }
    if (lane == 0) {
        #pragma unroll
        for (int e = 0; e < 8; e++) a[e] += br[e];
        int e0 = 0; float l0 = a[0];
        #pragma unroll
        for (int e = 1; e < 8; e++) if (a[e] > l0) { l0 = a[e]; e0 = e; }
        int e1 = -1; float l1 = -1e30f;
        #pragma unroll
        for (int e = 0; e < 8; e++) if (e != e0 && a[e] > l1) { l1 = a[e]; e1 = e; }
        // normalized top-2 softmax weights (softmax is monotone; denominators cancel)
        float w0 = 1.f / (1.f + expf(l1 - l0));
        float w1 = 1.f / (1.f + expf(l0 - l1));
        g_expert[2*tok]   = e0;  g_expert[2*tok+1] = e1;
        g_gate[2*tok]     = w0;  g_gate[2*tok+1]   = w1;
    }
}

// ---------------- 2) FCFS positions + per-expert gather lists ----------------
__global__ void assign_kernel() {
    __shared__ int sc[1024][9];  // padded to kill bank conflicts
    const int t = threadIdx.x;
    const int base = t * 16;     // 1024 * 16 = 16384 assignments

    #pragma unroll
    for (int e = 0; e < 8; e++) sc[t][e] = 0;
    for (int i = 0; i < 16; i++) sc[t][g_expert[base + i]]++;

    int loc[8], run[8];
    #pragma unroll
    for (int e = 0; e < 8; e++) { loc[e] = sc[t][e]; run[e] = loc[e]; }
    __syncthreads();

    // Hillis-Steele inclusive scan over threads, all 8 experts at once
    for (int off = 1; off < 1024; off <<= 1) {
        int add[8];
        #pragma unroll
        for (int e = 0; e < 8; e++) add[e] = (t >= off) ? sc[t - off][e] : 0;
        __syncthreads();
        #pragma unroll
        for (int e = 0; e < 8; e++) { run[e] += add[e]; sc[t][e] = run[e]; }
        __syncthreads();
    }
    if (t == 1023) {
        #pragma unroll
        for (int e = 0; e < 8; e++)
            g_count[e] = run[e] < CAPACITY ? run[e] : CAPACITY;
    }
    // exclusive base, then replay to place each assignment
    #pragma unroll
    for (int e = 0; e < 8; e++) sc[t][e] = run[e] - loc[e];
    for (int i = 0; i < 16; i++) {
        int a = base + i;
        int e = g_expert[a];
        int p = sc[t][e]++;
        g_pos[a] = p;
        if (p < CAPACITY) g_rowtok[e * CAPACITY + p] = a >> 1;  // token id
    }
}

// ---------------- 3) grouped tf32 GEMM, 128x128x16, cp.async double-buffer ----------
// FIRST=true : h = gelu(gather(x) @ W1[e] + b1[e])      (K=1024, N=4096)
// FIRST=false: y = h @ W2[e] + b2[e]                     (K=4096, N=1024)
template <bool FIRST>
__global__ __launch_bounds__(256, 2)
void moe_gemm(const float* __restrict__ X,
              const float* __restrict__ W,
              const float* __restrict__ bias) {
    constexpr int KTOT = FIRST ? D_MODEL : F_FF;
    constexpr int NTOT = FIRST ? F_FF : D_MODEL;
    constexpr int KIT  = KTOT / 16;

    __shared__ float As[2][128][20];   // padded: conflict-free fragment loads
    __shared__ float Bs[2][16][136];

    const int e = blockIdx.z, mt = blockIdx.y, nt = blockIdx.x;
    const int cnt = g_count[e];
    if (mt * 128 >= cnt) return;       // whole tile beyond this expert's rows

    const int tid = threadIdx.x, lane = tid & 31, warp = tid >> 5;
    const int wm = warp & 3, wn = warp >> 2;   // 4 (M) x 2 (N) warps -> 32x64 warp tiles

    const float* Ain = FIRST ? X : (const float*)g_h;
    float*       Cout = FIRST ? (float*)g_h : (float*)g_y;

    // per-thread load assignments: 2 chunks of 16B for A, 2 for B
    const float* asrc[2]; uint32_t adst[2];
    const float* bsrc[2]; uint32_t bdst[2];
    #pragma unroll
    for (int j = 0; j < 2; j++) {
        int c = tid + j * 256;
        int arow = c >> 2, aseg = (c & 3) * 4;
        if (FIRST) {
            int gr  = mt * 128 + arow;
            int tkr = (gr < cnt) ? g_rowtok[e * CAPACITY + gr] : 0;  // safe garbage row
            asrc[j] = Ain + (size_t)tkr * KTOT + aseg;
        } else {
            asrc[j] = Ain + ((size_t)e * CAPACITY + mt * 128 + arow) * (size_t)KTOT + aseg;
        }
        adst[j] = su32(&As[0][arow][aseg]);
        int brow = c >> 5, bseg = (c & 31) * 4;
        bsrc[j] = W + ((size_t)e * KTOT + brow) * (size_t)NTOT + (size_t)nt * 128 + bseg;
        bdst[j] = su32(&Bs[0][brow][bseg]);
    }
    constexpr uint32_t ASTAGE = 128 * 20 * 4;
    constexpr uint32_t BSTAGE = 16 * 136 * 4;

    float acc[2][8][4];
    #pragma unroll
    for (int mf = 0; mf < 2; mf++)
        #pragma unroll
        for (int nf = 0; nf < 8; nf++)
            #pragma unroll
            for (int q = 0; q < 4; q++) acc[mf][nf][q] = 0.f;

    // prologue: stage 0
    #pragma unroll
    for (int j = 0; j < 2; j++) { cpa16(adst[j], asrc[j]); cpa16(bdst[j], bsrc[j]); }
    cp_commit();

    #pragma unroll 1
    for (int kt = 0; kt < KIT; kt++) {
        const int s = kt & 1;
        cp_wait0();
        __syncthreads();
        if (kt + 1 < KIT) {
            const int s2 = s ^ 1;
            #pragma unroll
            for (int j = 0; j < 2; j++) {
                cpa16(adst[j] + s2 * ASTAGE, asrc[j] + (size_t)(kt + 1) * 16);
                cpa16(bdst[j] + s2 * BSTAGE, bsrc[j] + (size_t)(kt + 1) * 16 * NTOT);
            }
            cp_commit();
        }
        // compute this stage: two k=8 steps
        #pragma unroll
        for (int kk = 0; kk < 16; kk += 8) {
            const int kc = kk + (lane & 3);
            uint32_t af[2][4];
            #pragma unroll
            for (int mf = 0; mf < 2; mf++) {
                int r = wm * 32 + mf * 16 + (lane >> 2);
                af[mf][0] = f2tf(As[s][r    ][kc]);
                af[mf][1] = f2tf(As[s][r + 8][kc]);
                af[mf][2] = f2tf(As[s][r    ][kc + 4]);
                af[mf][3] = f2tf(As[s][r + 8][kc + 4]);
            }
            #pragma unroll
            for (int nf = 0; nf < 8; nf++) {
                int cn = wn * 64 + nf * 8 + (lane >> 2);
                uint32_t b0 = f2tf(Bs[s][kc    ][cn]);
                uint32_t b1 = f2tf(Bs[s][kc + 4][cn]);
                mma_tf32(acc[0][nf], af[0], b0, b1);
                mma_tf32(acc[1][nf], af[1], b0, b1);
            }
        }
    }

    // epilogue: bias (+gelu), write C
    const float* bp = bias + (size_t)e * NTOT + (size_t)nt * 128 + wn * 64;
    float* cb = Cout + ((size_t)e * CAPACITY + mt * 128 + wm * 32) * (size_t)NTOT
                     + (size_t)nt * 128 + wn * 64;
    #pragma unroll
    for (int mf = 0; mf < 2; mf++) {
        #pragma unroll
        for (int nf = 0; nf < 8; nf++) {
            int r  = mf * 16 + (lane >> 2);
            int cn = nf * 8 + 2 * (lane & 3);
            float bb0 = bp[cn], bb1 = bp[cn + 1];
            float v0 = acc[mf][nf][0] + bb0, v1 = acc[mf][nf][1] + bb1;
            float v2 = acc[mf][nf][2] + bb0, v3 = acc[mf][nf][3] + bb1;
            if (FIRST) {
                v0 = gelu_exact(v0); v1 = gelu_exact(v1);
                v2 = gelu_exact(v2); v3 = gelu_exact(v3);
            }
            *(float2*)(cb + (size_t)r * NTOT + cn)       = make_float2(v0, v1);
            *(float2*)(cb + (size_t)(r + 8) * NTOT + cn) = make_float2(v2, v3);
        }
    }
}

// ---------------- 4) combine: out[t] = sum_k w_k * y[e_k, pos_k]  (no atomics) ------
__global__ void combine_kernel(float* __restrict__ out) {
    const int idx = blockIdx.x * blockDim.x + threadIdx.x;   // exact T*d coverage
    const int tok = idx >> 10;
    const int col = idx & (D_MODEL - 1);
    float acc = 0.f;
    #pragma unroll
    for (int kk = 0; kk < 2; kk++) {
        int a = 2 * tok + kk;
        int p = g_pos[a];
        if (p < CAPACITY) {
            int ee = g_expert[a];
            acc += g_gate[a] * g_y[((size_t)ee * CAPACITY + p) * D_MODEL + col];
        }
    }
    out[idx] = acc;
}

// ---------------- launch ----------------
extern "C" void kernel_launch(void* const* d_in, const int* in_sizes, int n_in,
                              void* d_out, int out_size) {
    (void)in_sizes; (void)n_in; (void)out_size;
    const float* x  = (const float*)d_in[0];
    const float* Wr = (const float*)d_in[1];
    const float* br = (const float*)d_in[2];
    const float* W1 = (const float*)d_in[3];
    const float* b1 = (const float*)d_in[4];
    const float* W2 = (const float*)d_in[5];
    const float* b2 = (const float*)d_in[6];
    float* out = (float*)d_out;

    router_kernel<<<T_TOK / 8, 256>>>(x, Wr, br);
    assign_kernel<<<1, 1024>>>();
    moe_gemm<true ><<<dim3(F_FF / 128,    CAPACITY / 128, N_EXP), 256>>>(x,       W1, b1);
    moe_gemm<false><<<dim3(D_MODEL / 128, CAPACITY / 128, N_EXP), 256>>>(nullptr, W2, b2);
    combine_kernel<<<(T_TOK * D_MODEL) / 256, 256>>>(out);
}

// round 9
// speedup vs baseline: 1.0010x; 1.0010x over previous
#include <cuda_runtime.h>
#include <cstdint>
#include <cmath>
#include <math.h>

// Problem constants (fixed by setup_inputs)
#define T_TOK    8192
#define D_MODEL  1024
#define F_FF     4096
#define N_EXP    8
#define CAPACITY 2560          // ceil(1.25 * 8192*2 / 8)
#define NASSIGN  (T_TOK * 2)

// ---------------- scratch (device globals: no allocation allowed) ----------------
__device__ int   g_expert[NASSIGN];
__device__ float g_gate[NASSIGN];
__device__ int   g_pos[NASSIGN];
__device__ int   g_count[N_EXP];
__device__ int   g_rowtok[N_EXP * CAPACITY];
__device__ float g_h[(size_t)N_EXP * CAPACITY * F_FF];    // 335 MB
__device__ float g_y[(size_t)N_EXP * CAPACITY * D_MODEL]; //  84 MB

// ---------------- small helpers ----------------
__device__ __forceinline__ uint32_t su32(const void* p) {
    return (uint32_t)__cvta_generic_to_shared(p);
}
__device__ __forceinline__ uint32_t f2tf(float f) {
    uint32_t r; asm("cvt.rna.tf32.f32 %0, %1;" : "=r"(r) : "f"(f)); return r;
}
__device__ __forceinline__ void cpa16(uint32_t d, const void* s) {
    asm volatile("cp.async.cg.shared.global [%0], [%1], 16;" :: "r"(d), "l"(s));
}
__device__ __forceinline__ void cp_commit() { asm volatile("cp.async.commit_group;"); }
__device__ __forceinline__ void cp_wait0()  { asm volatile("cp.async.wait_group 0;" ::: "memory"); }

__device__ __forceinline__ void mma_tf32(float* c, const uint32_t* a, uint32_t b0, uint32_t b1) {
    asm volatile(
        "mma.sync.aligned.m16n8k8.row.col.f32.tf32.tf32.f32 "
        "{%0,%1,%2,%3}, {%4,%5,%6,%7}, {%8,%9}, {%0,%1,%2,%3};"
        : "+f"(c[0]), "+f"(c[1]), "+f"(c[2]), "+f"(c[3])
        : "r"(a[0]), "r"(a[1]), "r"(a[2]), "r"(a[3]), "r"(b0), "r"(b1));
}

__device__ __forceinline__ float gelu_exact(float v) {
    return 0.5f * v * (1.0f + erff(v * 0.70710678118654752440f));
}

// ---------------- 1) router: logits -> top2 -> normalized weights ----------------
__global__ void router_kernel(const float* __restrict__ x,
                              const float* __restrict__ Wr,
                              const float* __restrict__ br) {
    __shared__ float sW[D_MODEL * N_EXP];  // 32 KB
    const int tid = threadIdx.x;
    for (int i = tid; i < D_MODEL * N_EXP / 4; i += blockDim.x)
        ((float4*)sW)[i] = ((const float4*)Wr)[i];
    __syncthreads();

    const int warp = tid >> 5, lane = tid & 31;
    const int tok = blockIdx.x * 8 + warp;
    const float* xr = x + (size_t)tok * D_MODEL;

    float a[8] = {0.f,0.f,0.f,0.f,0.f,0.f,0.f,0.f};
    for (int i = lane; i < D_MODEL; i += 32) {
        float xv = xr[i];
        const float* w = sW + i * N_EXP;
        #pragma unroll
        for (int e = 0; e < 8; e++) a[e] += xv * w[e];
    }
    #pragma unroll
    for (int e = 0; e < 8; e++) {
        #pragma unroll
        for (int off = 16; off; off >>= 1)
            a[e] += __shfl_xor_sync(0xffffffffu, a[e], off);
    }
    if (lane == 0) {
        #pragma unroll
        for (int e = 0; e < 8; e++) a[e] += br[e];
        int e0 = 0; float l0 = a[0];
        #pragma unroll
        for (int e = 1; e < 8; e++) if (a[e] > l0) { l0 = a[e]; e0 = e; }
        int e1 = -1; float l1 = -1e30f;
        #pragma unroll
        for (int e = 0; e < 8; e++) if (e != e0 && a[e] > l1) { l1 = a[e]; e1 = e; }
        // normalized top-2 softmax weights (softmax is monotone; denominators cancel)
        float w0 = 1.f / (1.f + expf(l1 - l0));
        float w1 = 1.f / (1.f + expf(l0 - l1));
        g_expert[2*tok]   = e0;  g_expert[2*tok+1] = e1;
        g_gate[2*tok]     = w0;  g_gate[2*tok+1]   = w1;
    }
}

// ---------------- 2) FCFS positions + per-expert gather lists ----------------
__global__ void assign_kernel() {
    __shared__ int sc[1024][9];  // padded to kill bank conflicts
    const int t = threadIdx.x;
    const int base = t * 16;     // 1024 * 16 = 16384 assignments

    #pragma unroll
    for (int e = 0; e < 8; e++) sc[t][e] = 0;
    for (int i = 0; i < 16; i++) sc[t][g_expert[base + i]]++;

    int loc[8], run[8];
    #pragma unroll
    for (int e = 0; e < 8; e++) { loc[e] = sc[t][e]; run[e] = loc[e]; }
    __syncthreads();

    // Hillis-Steele inclusive scan over threads, all 8 experts at once
    for (int off = 1; off < 1024; off <<= 1) {
        int add[8];
        #pragma unroll
        for (int e = 0; e < 8; e++) add[e] = (t >= off) ? sc[t - off][e] : 0;
        __syncthreads();
        #pragma unroll
        for (int e = 0; e < 8; e++) { run[e] += add[e]; sc[t][e] = run[e]; }
        __syncthreads();
    }
    if (t == 1023) {
        #pragma unroll
        for (int e = 0; e < 8; e++)
            g_count[e] = run[e] < CAPACITY ? run[e] : CAPACITY;
    }
    // exclusive base, then replay to place each assignment
    #pragma unroll
    for (int e = 0; e < 8; e++) sc[t][e] = run[e] - loc[e];
    for (int i = 0; i < 16; i++) {
        int a = base + i;
        int e = g_expert[a];
        int p = sc[t][e]++;
        g_pos[a] = p;
        if (p < CAPACITY) g_rowtok[e * CAPACITY + p] = a >> 1;  // token id
    }
}

// ---------------- 3) grouped tf32 GEMM, 128x128x16, cp.async double-buffer ----------
// FIRST=true : h = gelu(gather(x) @ W1[e] + b1[e])      (K=1024, N=4096)
// FIRST=false: y = h @ W2[e] + b2[e]                     (K=4096, N=1024)
template <bool FIRST>
__global__ __launch_bounds__(256, 2)
void moe_gemm(const float* __restrict__ X,
              const float* __restrict__ W,
              const float* __restrict__ bias) {
    constexpr int KTOT = FIRST ? D_MODEL : F_FF;
    constexpr int NTOT = FIRST ? F_FF : D_MODEL;
    constexpr int KIT  = KTOT / 16;

    __shared__ float As[2][128][20];   // padded: conflict-free fragment loads
    __shared__ float Bs[2][16][136];

    const int e = blockIdx.z, mt = blockIdx.y, nt = blockIdx.x;
    const int cnt = g_count[e];
    if (mt * 128 >= cnt) return;       // whole tile beyond this expert's rows

    const int tid = threadIdx.x, lane = tid & 31, warp = tid >> 5;
    const int wm = warp & 3, wn = warp >> 2;   // 4 (M) x 2 (N) warps -> 32x64 warp tiles

    const float* Ain = FIRST ? X : (const float*)g_h;
    float*       Cout = FIRST ? (float*)g_h : (float*)g_y;

    // per-thread load assignments: 2 chunks of 16B for A, 2 for B
    const float* asrc[2]; uint32_t adst[2];
    const float* bsrc[2]; uint32_t bdst[2];
    #pragma unroll
    for (int j = 0; j < 2; j++) {
        int c = tid + j * 256;
        int arow = c >> 2, aseg = (c & 3) * 4;
        if (FIRST) {
            int gr  = mt * 128 + arow;
            int tkr = (gr < cnt) ? g_rowtok[e * CAPACITY + gr] : 0;  // safe garbage row
            asrc[j] = Ain + (size_t)tkr * KTOT + aseg;
        } else {
            asrc[j] = Ain + ((size_t)e * CAPACITY + mt * 128 + arow) * (size_t)KTOT + aseg;
        }
        adst[j] = su32(&As[0][arow][aseg]);
        int brow = c >> 5, bseg = (c & 31) * 4;
        bsrc[j] = W + ((size_t)e * KTOT + brow) * (size_t)NTOT + (size_t)nt * 128 + bseg;
        bdst[j] = su32(&Bs[0][brow][bseg]);
    }
    constexpr uint32_t ASTAGE = 128 * 20 * 4;
    constexpr uint32_t BSTAGE = 16 * 136 * 4;

    float acc[2][8][4];
    #pragma unroll
    for (int mf = 0; mf < 2; mf++)
        #pragma unroll
        for (int nf = 0; nf < 8; nf++)
            #pragma unroll
            for (int q = 0; q < 4; q++) acc[mf][nf][q] = 0.f;

    // prologue: stage 0
    #pragma unroll
    for (int j = 0; j < 2; j++) { cpa16(adst[j], asrc[j]); cpa16(bdst[j], bsrc[j]); }
    cp_commit();

    #pragma unroll 1
    for (int kt = 0; kt < KIT; kt++) {
        const int s = kt & 1;
        cp_wait0();
        __syncthreads();
        if (kt + 1 < KIT) {
            const int s2 = s ^ 1;
            #pragma unroll
            for (int j = 0; j < 2; j++) {
                cpa16(adst[j] + s2 * ASTAGE, asrc[j] + (size_t)(kt + 1) * 16);
                cpa16(bdst[j] + s2 * BSTAGE, bsrc[j] + (size_t)(kt + 1) * 16 * NTOT);
            }
            cp_commit();
        }
        // compute this stage: two k=8 steps
        #pragma unroll
        for (int kk = 0; kk < 16; kk += 8) {
            const int kc = kk + (lane & 3);
            uint32_t af[2][4];
            #pragma unroll
            for (int mf = 0; mf < 2; mf++) {
                int r = wm * 32 + mf * 16 + (lane >> 2);
                af[mf][0] = f2tf(As[s][r    ][kc]);
                af[mf][1] = f2tf(As[s][r + 8][kc]);
                af[mf][2] = f2tf(As[s][r    ][kc + 4]);
                af[mf][3] = f2tf(As[s][r + 8][kc + 4]);
            }
            #pragma unroll
            for (int nf = 0; nf < 8; nf++) {
                int cn = wn * 64 + nf * 8 + (lane >> 2);
                uint32_t b0 = f2tf(Bs[s][kc    ][cn]);
                uint32_t b1 = f2tf(Bs[s][kc + 4][cn]);
                mma_tf32(acc[0][nf], af[0], b0, b1);
                mma_tf32(acc[1][nf], af[1], b0, b1);
            }
        }
    }

    // epilogue: bias (+gelu), write C
    const float* bp = bias + (size_t)e * NTOT + (size_t)nt * 128 + wn * 64;
    float* cb = Cout + ((size_t)e * CAPACITY + mt * 128 + wm * 32) * (size_t)NTOT
                     + (size_t)nt * 128 + wn * 64;
    #pragma unroll
    for (int mf = 0; mf < 2; mf++) {
        #pragma unroll
        for (int nf = 0; nf < 8; nf++) {
            int r  = mf * 16 + (lane >> 2);
            int cn = nf * 8 + 2 * (lane & 3);
            float bb0 = bp[cn], bb1 = bp[cn + 1];
            float v0 = acc[mf][nf][0] + bb0, v1 = acc[mf][nf][1] + bb1;
            float v2 = acc[mf][nf][2] + bb0, v3 = acc[mf][nf][3] + bb1;
            if (FIRST) {
                v0 = gelu_exact(v0); v1 = gelu_exact(v1);
                v2 = gelu_exact(v2); v3 = gelu_exact(v3);
            }
            *(float2*)(cb + (size_t)r * NTOT + cn)       = make_float2(v0, v1);
            *(float2*)(cb + (size_t)(r + 8) * NTOT + cn) = make_float2(v2, v3);
        }
    }
}

// ---------------- 4) combine: out[t] = sum_k w_k * y[e_k, pos_k]  (no atomics) ------
__global__ void combine_kernel(float* __restrict__ out) {
    const int idx = blockIdx.x * blockDim.x + threadIdx.x;   // exact T*d coverage
    const int tok = idx >> 10;
    const int col = idx & (D_MODEL - 1);
    float acc = 0.f;
    #pragma unroll
    for (int kk = 0; kk < 2; kk++) {
        int a = 2 * tok + kk;
        int p = g_pos[a];
        if (p < CAPACITY) {
            int ee = g_expert[a];
            acc += g_gate[a] * g_y[((size_t)ee * CAPACITY + p) * D_MODEL + col];
        }
    }
    out[idx] = acc;
}

// ---------------- launch ----------------
extern "C" void kernel_launch(void* const* d_in, const int* in_sizes, int n_in,
                              void* d_out, int out_size) {
    (void)in_sizes; (void)n_in; (void)out_size;
    const float* x  = (const float*)d_in[0];
    const float* Wr = (const float*)d_in[1];
    const float* br = (const float*)d_in[2];
    const float* W1 = (const float*)d_in[3];
    const float* b1 = (const float*)d_in[4];
    const float* W2 = (const float*)d_in[5];
    const float* b2 = (const float*)d_in[6];
    float* out = (float*)d_out;

    router_kernel<<<T_TOK / 8, 256>>>(x, Wr, br);
    assign_kernel<<<1, 1024>>>();
    moe_gemm<true ><<<dim3(F_FF / 128,    CAPACITY / 128, N_EXP), 256>>>(x,       W1, b1);
    moe_gemm<false><<<dim3(D_MODEL / 128, CAPACITY / 128, N_EXP), 256>>>(nullptr, W2, b2);
    combine_kernel<<<(T_TOK * D_MODEL) / 256, 256>>>(out);
}

// round 10
// speedup vs baseline: 1.0255x; 1.0246x over previous
#include <cuda_runtime.h>
#include <cstdint>
#include <cmath>
#include <math.h>

// Problem constants (fixed by setup_inputs)
#define T_TOK    8192
#define D_MODEL  1024
#define F_FF     4096
#define N_EXP    8
#define CAPACITY 2560          // ceil(1.25 * 8192*2 / 8)
#define NASSIGN  (T_TOK * 2)

// ---------------- scratch (device globals: no allocation allowed) ----------------
__device__ int      g_expert[NASSIGN];
__device__ float    g_gate[NASSIGN];
__device__ int      g_pos[NASSIGN];
__device__ int      g_count[N_EXP];
__device__ int      g_rowtok[N_EXP * CAPACITY];
__device__ uint32_t g_h[(size_t)N_EXP * CAPACITY * F_FF];    // 335 MB (tf32 bits)
__device__ float    g_y[(size_t)N_EXP * CAPACITY * D_MODEL]; //  84 MB
// pre-converted tf32 operands (valid fp32 bit patterns with low mantissa zeroed)
__device__ uint32_t g_xt [(size_t)T_TOK * D_MODEL];              //  33 MB
__device__ uint32_t g_w1t[(size_t)N_EXP * D_MODEL * F_FF];       // 134 MB
__device__ uint32_t g_w2t[(size_t)N_EXP * F_FF * D_MODEL];       // 134 MB

// ---------------- small helpers ----------------
__device__ __forceinline__ uint32_t su32(const void* p) {
    return (uint32_t)__cvta_generic_to_shared(p);
}
__device__ __forceinline__ uint32_t f2tf(float f) {
    uint32_t r; asm("cvt.rna.tf32.f32 %0, %1;" : "=r"(r) : "f"(f)); return r;
}
__device__ __forceinline__ void cpa16(uint32_t d, const void* s) {
    asm volatile("cp.async.cg.shared.global [%0], [%1], 16;" :: "r"(d), "l"(s));
}
__device__ __forceinline__ void cp_commit() { asm volatile("cp.async.commit_group;"); }
__device__ __forceinline__ void cp_wait0()  { asm volatile("cp.async.wait_group 0;" ::: "memory"); }

__device__ __forceinline__ void mma_tf32(float* c, const uint32_t* a, uint32_t b0, uint32_t b1) {
    asm volatile(
        "mma.sync.aligned.m16n8k8.row.col.f32.tf32.tf32.f32 "
        "{%0,%1,%2,%3}, {%4,%5,%6,%7}, {%8,%9}, {%0,%1,%2,%3};"
        : "+f"(c[0]), "+f"(c[1]), "+f"(c[2]), "+f"(c[3])
        : "r"(a[0]), "r"(a[1]), "r"(a[2]), "r"(a[3]), "r"(b0), "r"(b1));
}

__device__ __forceinline__ float gelu_exact(float v) {
    return 0.5f * v * (1.0f + erff(v * 0.70710678118654752440f));
}

// ---------------- 0) tf32 pre-conversion (elementwise, float4-wide) ----------------
__global__ void tf32_conv_kernel(const float4* __restrict__ src,
                                 uint4* __restrict__ dst, int n4) {
    int i = blockIdx.x * blockDim.x + threadIdx.x;
    if (i < n4) {
        float4 v = src[i];
        uint4 o;
        o.x = f2tf(v.x); o.y = f2tf(v.y); o.z = f2tf(v.z); o.w = f2tf(v.w);
        dst[i] = o;
    }
}

// ---------------- 1) router: logits -> top2 -> normalized weights ----------------
__global__ void router_kernel(const float* __restrict__ x,
                              const float* __restrict__ Wr,
                              const float* __restrict__ br) {
    __shared__ float sW[D_MODEL * N_EXP];  // 32 KB
    const int tid = threadIdx.x;
    for (int i = tid; i < D_MODEL * N_EXP / 4; i += blockDim.x)
        ((float4*)sW)[i] = ((const float4*)Wr)[i];
    __syncthreads();

    const int warp = tid >> 5, lane = tid & 31;
    const int tok = blockIdx.x * 8 + warp;
    const float* xr = x + (size_t)tok * D_MODEL;

    float a[8] = {0.f,0.f,0.f,0.f,0.f,0.f,0.f,0.f};
    for (int i = lane; i < D_MODEL; i += 32) {
        float xv = xr[i];
        const float* w = sW + i * N_EXP;
        #pragma unroll
        for (int e = 0; e < 8; e++) a[e] += xv * w[e];
    }
    #pragma unroll
    for (int e = 0; e < 8; e++) {
        #pragma unroll
        for (int off = 16; off; off >>= 1)
            a[e] += __shfl_xor_sync(0xffffffffu, a[e], off);
    }
    if (lane == 0) {
        #pragma unroll
        for (int e = 0; e < 8; e++) a[e] += br[e];
        int e0 = 0; float l0 = a[0];
        #pragma unroll
        for (int e = 1; e < 8; e++) if (a[e] > l0) { l0 = a[e]; e0 = e; }
        int e1 = -1; float l1 = -1e30f;
        #pragma unroll
        for (int e = 0; e < 8; e++) if (e != e0 && a[e] > l1) { l1 = a[e]; e1 = e; }
        // normalized top-2 softmax weights (softmax is monotone; denominators cancel)
        float w0 = 1.f / (1.f + expf(l1 - l0));
        float w1 = 1.f / (1.f + expf(l0 - l1));
        g_expert[2*tok]   = e0;  g_expert[2*tok+1] = e1;
        g_gate[2*tok]     = w0;  g_gate[2*tok+1]   = w1;
    }
}

// ---------------- 2) FCFS positions + per-expert gather lists ----------------
__global__ void assign_kernel() {
    __shared__ int sc[1024][9];  // padded to kill bank conflicts
    const int t = threadIdx.x;
    const int base = t * 16;     // 1024 * 16 = 16384 assignments

    #pragma unroll
    for (int e = 0; e < 8; e++) sc[t][e] = 0;
    for (int i = 0; i < 16; i++) sc[t][g_expert[base + i]]++;

    int loc[8], run[8];
    #pragma unroll
    for (int e = 0; e < 8; e++) { loc[e] = sc[t][e]; run[e] = loc[e]; }
    __syncthreads();

    // Hillis-Steele inclusive scan over threads, all 8 experts at once
    for (int off = 1; off < 1024; off <<= 1) {
        int add[8];
        #pragma unroll
        for (int e = 0; e < 8; e++) add[e] = (t >= off) ? sc[t - off][e] : 0;
        __syncthreads();
        #pragma unroll
        for (int e = 0; e < 8; e++) { run[e] += add[e]; sc[t][e] = run[e]; }
        __syncthreads();
    }
    if (t == 1023) {
        #pragma unroll
        for (int e = 0; e < 8; e++)
            g_count[e] = run[e] < CAPACITY ? run[e] : CAPACITY;
    }
    // exclusive base, then replay to place each assignment
    #pragma unroll
    for (int e = 0; e < 8; e++) sc[t][e] = run[e] - loc[e];
    for (int i = 0; i < 16; i++) {
        int a = base + i;
        int e = g_expert[a];
        int p = sc[t][e]++;
        g_pos[a] = p;
        if (p < CAPACITY) g_rowtok[e * CAPACITY + p] = a >> 1;  // token id
    }
}

// ---------------- 3) grouped tf32 GEMM, 128x128x16, cp.async double-buffer ----------
// Operands arrive pre-converted to tf32 bit patterns: ZERO cvt in the inner loop.
// FIRST=true : h = tf32(gelu(gather(xt) @ W1t[e] + b1[e]))   (K=1024, N=4096)
// FIRST=false: y = h @ W2t[e] + b2[e]                        (K=4096, N=1024)
template <bool FIRST>
__global__ __launch_bounds__(256, 2)
void moe_gemm(const uint32_t* __restrict__ X,
              const uint32_t* __restrict__ W,
              const float* __restrict__ bias) {
    constexpr int KTOT = FIRST ? D_MODEL : F_FF;
    constexpr int NTOT = FIRST ? F_FF : D_MODEL;
    constexpr int KIT  = KTOT / 16;

    __shared__ uint32_t As[2][128][20];   // padded: conflict-free fragment loads
    __shared__ uint32_t Bs[2][16][136];

    const int e = blockIdx.z, mt = blockIdx.y, nt = blockIdx.x;
    const int cnt = g_count[e];
    if (mt * 128 >= cnt) return;       // whole tile beyond this expert's rows

    const int tid = threadIdx.x, lane = tid & 31, warp = tid >> 5;
    const int wm = warp & 3, wn = warp >> 2;   // 4 (M) x 2 (N) warps -> 32x64 warp tiles

    const uint32_t* Ain = FIRST ? X : (const uint32_t*)g_h;

    // per-thread load assignments: 2 chunks of 16B for A, 2 for B
    const uint32_t* asrc[2]; uint32_t adst[2];
    const uint32_t* bsrc[2]; uint32_t bdst[2];
    #pragma unroll
    for (int j = 0; j < 2; j++) {
        int c = tid + j * 256;
        int arow = c >> 2, aseg = (c & 3) * 4;
        if (FIRST) {
            int gr  = mt * 128 + arow;
            int tkr = (gr < cnt) ? g_rowtok[e * CAPACITY + gr] : 0;  // safe garbage row
            asrc[j] = Ain + (size_t)tkr * KTOT + aseg;
        } else {
            asrc[j] = Ain + ((size_t)e * CAPACITY + mt * 128 + arow) * (size_t)KTOT + aseg;
        }
        adst[j] = su32(&As[0][arow][aseg]);
        int brow = c >> 5, bseg = (c & 31) * 4;
        bsrc[j] = W + ((size_t)e * KTOT + brow) * (size_t)NTOT + (size_t)nt * 128 + bseg;
        bdst[j] = su32(&Bs[0][brow][bseg]);
    }
    constexpr uint32_t ASTAGE = 128 * 20 * 4;
    constexpr uint32_t BSTAGE = 16 * 136 * 4;

    float acc[2][8][4];
    #pragma unroll
    for (int mf = 0; mf < 2; mf++)
        #pragma unroll
        for (int nf = 0; nf < 8; nf++)
            #pragma unroll
            for (int q = 0; q < 4; q++) acc[mf][nf][q] = 0.f;

    // prologue: stage 0
    #pragma unroll
    for (int j = 0; j < 2; j++) { cpa16(adst[j], asrc[j]); cpa16(bdst[j], bsrc[j]); }
    cp_commit();

    #pragma unroll 1
    for (int kt = 0; kt < KIT; kt++) {
        const int s = kt & 1;
        cp_wait0();
        __syncthreads();
        if (kt + 1 < KIT) {
            const int s2 = s ^ 1;
            #pragma unroll
            for (int j = 0; j < 2; j++) {
                cpa16(adst[j] + s2 * ASTAGE, asrc[j] + (size_t)(kt + 1) * 16);
                cpa16(bdst[j] + s2 * BSTAGE, bsrc[j] + (size_t)(kt + 1) * 16 * NTOT);
            }
            cp_commit();
        }
        // compute this stage: two k=8 steps — pure LDS + HMMA, no conversions
        #pragma unroll
        for (int kk = 0; kk < 16; kk += 8) {
            const int kc = kk + (lane & 3);
            uint32_t af[2][4];
            #pragma unroll
            for (int mf = 0; mf < 2; mf++) {
                int r = wm * 32 + mf * 16 + (lane >> 2);
                af[mf][0] = As[s][r    ][kc];
                af[mf][1] = As[s][r + 8][kc];
                af[mf][2] = As[s][r    ][kc + 4];
                af[mf][3] = As[s][r + 8][kc + 4];
            }
            #pragma unroll
            for (int nf = 0; nf < 8; nf++) {
                int cn = wn * 64 + nf * 8 + (lane >> 2);
                uint32_t b0 = Bs[s][kc    ][cn];
                uint32_t b1 = Bs[s][kc + 4][cn];
                mma_tf32(acc[0][nf], af[0], b0, b1);
                mma_tf32(acc[1][nf], af[1], b0, b1);
            }
        }
    }

    // epilogue: bias (+gelu), write C
    const float* bp = bias + (size_t)e * NTOT + (size_t)nt * 128 + wn * 64;
    const size_t cbase = ((size_t)e * CAPACITY + mt * 128 + wm * 32) * (size_t)NTOT
                       + (size_t)nt * 128 + wn * 64;
    #pragma unroll
    for (int mf = 0; mf < 2; mf++) {
        #pragma unroll
        for (int nf = 0; nf < 8; nf++) {
            int r  = mf * 16 + (lane >> 2);
            int cn = nf * 8 + 2 * (lane & 3);
            float bb0 = bp[cn], bb1 = bp[cn + 1];
            float v0 = acc[mf][nf][0] + bb0, v1 = acc[mf][nf][1] + bb1;
            float v2 = acc[mf][nf][2] + bb0, v3 = acc[mf][nf][3] + bb1;
            if (FIRST) {
                // store h already tf32-rounded: GEMM2 loads with zero cvt
                uint32_t u0 = f2tf(gelu_exact(v0)), u1 = f2tf(gelu_exact(v1));
                uint32_t u2 = f2tf(gelu_exact(v2)), u3 = f2tf(gelu_exact(v3));
                *(uint2*)(g_h + cbase + (size_t)r * NTOT + cn)       = make_uint2(u0, u1);
                *(uint2*)(g_h + cbase + (size_t)(r + 8) * NTOT + cn) = make_uint2(u2, u3);
            } else {
                *(float2*)(g_y + cbase + (size_t)r * NTOT + cn)       = make_float2(v0, v1);
                *(float2*)(g_y + cbase + (size_t)(r + 8) * NTOT + cn) = make_float2(v2, v3);
            }
        }
    }
}

// ---------------- 4) combine: out[t] = sum_k w_k * y[e_k, pos_k]  (no atomics) ------
__global__ void combine_kernel(float* __restrict__ out) {
    const int idx = blockIdx.x * blockDim.x + threadIdx.x;   // exact T*d coverage
    const int tok = idx >> 10;
    const int col = idx & (D_MODEL - 1);
    float acc = 0.f;
    #pragma unroll
    for (int kk = 0; kk < 2; kk++) {
        int a = 2 * tok + kk;
        int p = g_pos[a];
        if (p < CAPACITY) {
            int ee = g_expert[a];
            acc += g_gate[a] * g_y[((size_t)ee * CAPACITY + p) * D_MODEL + col];
        }
    }
    out[idx] = acc;
}

// ---------------- launch ----------------
extern "C" void kernel_launch(void* const* d_in, const int* in_sizes, int n_in,
                              void* d_out, int out_size) {
    (void)in_sizes; (void)n_in; (void)out_size;
    const float* x  = (const float*)d_in[0];
    const float* Wr = (const float*)d_in[1];
    const float* br = (const float*)d_in[2];
    const float* W1 = (const float*)d_in[3];
    const float* b1 = (const float*)d_in[4];
    const float* W2 = (const float*)d_in[5];
    const float* b2 = (const float*)d_in[6];
    float* out = (float*)d_out;

    uint32_t *xt_p, *w1t_p, *w2t_p;
    cudaGetSymbolAddress((void**)&xt_p,  g_xt);
    cudaGetSymbolAddress((void**)&w1t_p, g_w1t);
    cudaGetSymbolAddress((void**)&w2t_p, g_w2t);

    // pre-convert operands to tf32 bit patterns (weights reused 160x per GEMM)
    {
        const int nx = T_TOK * D_MODEL / 4;
        const int nw = N_EXP * D_MODEL * F_FF / 4;
        tf32_conv_kernel<<<(nx + 255) / 256, 256>>>((const float4*)x,  (uint4*)xt_p,  nx);
        tf32_conv_kernel<<<(nw + 255) / 256, 256>>>((const float4*)W1, (uint4*)w1t_p, nw);
        tf32_conv_kernel<<<(nw + 255) / 256, 256>>>((const float4*)W2, (uint4*)w2t_p, nw);
    }

    router_kernel<<<T_TOK / 8, 256>>>(x, Wr, br);
    assign_kernel<<<1, 1024>>>();
    moe_gemm<true ><<<dim3(F_FF / 128,    CAPACITY / 128, N_EXP), 256>>>(xt_p,    w1t_p, b1);
    moe_gemm<false><<<dim3(D_MODEL / 128, CAPACITY / 128, N_EXP), 256>>>(nullptr, w2t_p, b2);
    combine_kernel<<<(T_TOK * D_MODEL) / 256, 256>>>(out);
}